// round 14
// baseline (speedup 1.0000x reference)
#include <cuda_runtime.h>
#include <cuda_bf16.h>
#include <math.h>
#include <stdint.h>

// ---------------- scratch (no allocations allowed) ----------------
#define NGMAX   4096        // max local genes
#define GCAP    1024        // bucket capacity per gene (mean ~250, sigma ~16)
#define NCGMAX  2048000     // max n_cells * n_genes
#define NCELLMAX 65536      // cell index fits 16 bits

__device__ int    d_hist[NGMAX];             // per-gene cut count / cursor
__device__ int2   d_info[NGMAX * GCAP];      // bucketed: {cell | (g2<<16), coord bits}
__device__ int    d_counts[NCGMAX];
__device__ float4 d_prm[NGMAX * 32];         // {loc, 1/scale, -log(scale)-0.5*log(2pi), logit_w}
__device__ uint32_t d_latbf[NCELLMAX * 32];  // latent rows as bf16x2 (128 B per cell)
__device__ float  d_rwT[64 * NGMAX];         // gathered+transposed rho_weight: [l][g]
__device__ float  d_rbg[NGMAX];              // gathered rho_bias
__device__ double d_acc;                     // likelihood accumulator
__device__ int    d_done_f;                  // frag completion ticket

__device__ __forceinline__ uint32_t pack_bf16(float lo, float hi) {
    uint32_t r;
    asm("cvt.rn.bf16x2.f32 %0, %1, %2;" : "=r"(r) : "f"(hi), "f"(lo));
    return r;
}

// 256-bit load (Blackwell): two adjacent float4s in one instruction.
__device__ __forceinline__ void ldg256(const float4* p, float4& a, float4& b) {
    asm("ld.global.v8.f32 {%0,%1,%2,%3,%4,%5,%6,%7}, [%8];"
        : "=f"(a.x), "=f"(a.y), "=f"(a.z), "=f"(a.w),
          "=f"(b.x), "=f"(b.y), "=f"(b.z), "=f"(b.w)
        : "l"(p));
}

// ---------------- kernels ----------------

// zero scratch + precompute gathered per-gene parameter tables + bf16 latent
__global__ void k_zprep(const int* __restrict__ genes_oi,
                        const float* __restrict__ loc_w,
                        const float* __restrict__ scale_w,
                        const float* __restrict__ logit_w,
                        const float* __restrict__ rho_weight,
                        const float* __restrict__ rho_bias,
                        const float* __restrict__ latent,
                        int n_cells, int ncg, int ng) {
    int i = blockIdx.x * blockDim.x + threadIdx.x;
    int stride = gridDim.x * blockDim.x;
    int ncg4 = ncg >> 2;
    int4* c4 = (int4*)d_counts;
    int4 z4 = make_int4(0, 0, 0, 0);
    for (int j = i; j < ncg4; j += stride) c4[j] = z4;
    for (int j = (ncg4 << 2) + i; j < ncg; j += stride) d_counts[j] = 0;
    for (int j = i; j < ng; j += stride) d_hist[j] = 0;
    if (i == 0) { d_acc = 0.0; d_done_f = 0; }

    for (int j = i; j < ng * 32; j += stride) {
        int g = j >> 5, c = j & 31;
        int gene = genes_oi[g];
        float lwv = logit_w[gene * 32 + c];
        float loc = 1.0f / (1.0f + expf(-loc_w[gene * 32 + c]));
        float sc  = 1e-5f + expf(scale_w[gene * 32 + c]);
        d_prm[j] = make_float4(loc, 1.0f / sc, -logf(sc) - 0.91893853320467274f, lwv);
    }
    for (int j = i; j < ng * 64; j += stride) {
        int g = j % ng, l = j / ng;
        d_rwT[l * ng + g] = rho_weight[(size_t)genes_oi[g] * 64 + l];
    }
    for (int j = i; j < ng; j += stride) d_rbg[j] = rho_bias[genes_oi[j]];
    // latent -> bf16x2 rows
    for (int j = i; j < n_cells * 32; j += stride) {
        float2 v = *(const float2*)(latent + 2 * j);
        d_latbf[j] = pack_bf16(v.x, v.y);
    }
}

// Fused gather: direct-bucket scatter of cuts by gene (no scan needed) +
// fragment count histogram. One pass over clcg/clg/coords/lcg.
__global__ void __launch_bounds__(512) k_gather(
        const int* __restrict__ clcg,
        const int* __restrict__ clg,
        const float* __restrict__ coords,
        const int* __restrict__ lcg,
        int n_cuts, int n_frags, int ng) {
    int i0 = blockIdx.x * blockDim.x + threadIdx.x;
    int stride = gridDim.x * blockDim.x;
    for (int k = i0; k < n_cuts; k += stride) {
        int v = clcg[k];
        int g = v % ng;
        int cell = v / ng;
        int p = atomicAdd(&d_hist[g], 1);
        if (p < GCAP)
            d_info[(g << 10) + p] = make_int2(cell | (clg[k] << 16), __float_as_int(coords[k]));
    }
    for (int f = i0; f < n_frags; f += stride)
        atomicAdd(&d_counts[lcg[f]], 1);
}

// Mixture log-likelihood via tensor cores: one CTA per local gene, one warp
// per 16-cut tile. delta[16,32] = Lat[16,64](bf16) x W[64,32](bf16) with
// mma.sync.m16n8k16 (4 k-steps x 4 n-tiles).
// A path: cooperative full-line staging of 16 bf16 latent rows (4 LDG.128)
// into a swizzled per-warp smem tile + 4x ldmatrix.x4.
// prm path: 256-bit loads (v8.f32). B fragments in a 4 KB CTA-shared table,
// interleaved so each (ks,ns) pair is a single LDS.64.
__global__ void __launch_bounds__(256, 4) k_mix(
        const int* __restrict__ genes_oi,
        const float* __restrict__ logit_weight,
        int ng) {
    __shared__ uint32_t sbB[4 * 4 * 32 * 2];            // 4 KB, [ks][ns][lane][j]
    __shared__ __align__(16) unsigned char sA[8][2048]; // 16 KB: 16 rows x 128 B per warp
    __shared__ float wpart[8];
    int g = blockIdx.x;
    int lane = threadIdx.x & 31;
    int w = threadIdx.x >> 5;

    const float* lwg = logit_weight + (size_t)genes_oi[g] * 2048;

    // B-fragment table: entry ((ks*4+ns)*32 + le)*2 + j:
    // c = ns*8 + (le>>2), k0 = ks*16 + (le&3)*2 + j*8, packed {B[k0][c], B[k0+1][c]}
    for (int idx = threadIdx.x; idx < 1024; idx += 256) {
        int j  = idx & 1;
        int le = (idx >> 1) & 31;
        int ns = (idx >> 6) & 3;
        int ks = idx >> 8;
        int c  = ns * 8 + (le >> 2);
        int k0 = ks * 16 + (le & 3) * 2 + j * 8;
        sbB[idx] = pack_bf16(lwg[k0 * 32 + c], lwg[(k0 + 1) * 32 + c]);
    }
    int cnt = min(d_hist[g], GCAP);
    int s0 = g << 10;
    int s1 = s0 + cnt;
    __syncthreads();

    float acc = 0.0f;
    int r  = lane >> 2;
    int cq = (lane & 3) * 2;
    uint32_t wb = (uint32_t)__cvta_generic_to_shared(sA[w]);
    int lm_row = ((lane >> 3) & 1) * 8 + (lane & 7);
    int lm_half = lane >> 4;

    for (int ts = s0 + 16 * w; ts < s1; ts += 128) {
        int n = min(16, s1 - ts);

        // tile info: lanes 0..15 hold one cut each
        int ix = 0;
        float xl = 0.0f;
        if (lane < 16 && ts + lane < s1) {
            int2 ii = d_info[ts + lane];
            ix = ii.x;
            xl = __int_as_float(ii.y);
        }

        // ---- stage 16 bf16 rows (full-line cooperative, swizzled) ----
        __syncwarp();   // previous tile's ldmatrix reads complete
#pragma unroll
        for (int it = 0; it < 4; it++) {
            int q = it * 32 + lane;        // chunk id 0..127
            int row = q >> 3, ch = q & 7;
            int cell = __shfl_sync(0xffffffffu, ix, row) & 0xffff;
            uint4 v = *((const uint4*)d_latbf + cell * 8 + ch);
            uint32_t ad = wb + row * 128 + ((ch ^ (row & 7)) << 4);
            asm volatile("st.shared.v4.b32 [%0], {%1,%2,%3,%4};"
                         :: "r"(ad), "r"(v.x), "r"(v.y), "r"(v.z), "r"(v.w));
        }
        __syncwarp();

        // ---- mma: delta[16,32] via ldmatrix per k-step ----
        float d[4][4];
#pragma unroll
        for (int ns = 0; ns < 4; ns++)
#pragma unroll
            for (int j = 0; j < 4; j++) d[ns][j] = 0.0f;

#pragma unroll
        for (int ks = 0; ks < 4; ks++) {
            int chunk = ks * 2 + lm_half;
            uint32_t ad = wb + lm_row * 128 + ((chunk ^ (lm_row & 7)) << 4);
            uint32_t a0, a1, a2, a3;
            asm volatile("ldmatrix.sync.aligned.m8n8.x4.shared.b16 {%0,%1,%2,%3}, [%4];"
                         : "=r"(a0), "=r"(a1), "=r"(a2), "=r"(a3) : "r"(ad));
#pragma unroll
            for (int ns = 0; ns < 4; ns++) {
                uint2 bb = *(const uint2*)&sbB[((ks * 4 + ns) * 32 + lane) * 2];
                asm volatile(
                    "mma.sync.aligned.m16n8k16.row.col.f32.bf16.bf16.f32 "
                    "{%0,%1,%2,%3}, {%4,%5,%6,%7}, {%8,%9}, {%0,%1,%2,%3};"
                    : "+f"(d[ns][0]), "+f"(d[ns][1]), "+f"(d[ns][2]), "+f"(d[ns][3])
                    : "r"(a0), "r"(a1), "r"(a2), "r"(a3), "r"(bb.x), "r"(bb.y));
            }
        }

        // ---- epilogue: rows r and r+8, comps ns*8 + cq + {0,1} ----
        int ixA = __shfl_sync(0xffffffffu, ix, r);
        int ixB = __shfl_sync(0xffffffffu, ix, r + 8);
        float xA = __shfl_sync(0xffffffffu, xl, r);
        float xB = __shfl_sync(0xffffffffu, xl, r + 8);
        const float4* prmA = d_prm + (((unsigned)ixA) >> 16) * 32;
        const float4* prmB = d_prm + (((unsigned)ixB) >> 16) * 32;
        float eaA = 0.f, ebA = 0.f, eaB = 0.f, ebB = 0.f;
#pragma unroll
        for (int ns = 0; ns < 4; ns++) {
            int c0 = ns * 8 + cq;
            float4 pa0, pa1, pb0, pb1;
            ldg256(prmA + c0, pa0, pa1);
            ldg256(prmB + c0, pb0, pb1);
            float la, z, lb;
            la = d[ns][0] + pa0.w; z = (xA - pa0.x) * pa0.y;
            lb = fmaf(-0.5f * z, z, la + pa0.z);
            eaA += __expf(la); ebA += __expf(lb);
            la = d[ns][1] + pa1.w; z = (xA - pa1.x) * pa1.y;
            lb = fmaf(-0.5f * z, z, la + pa1.z);
            eaA += __expf(la); ebA += __expf(lb);
            la = d[ns][2] + pb0.w; z = (xB - pb0.x) * pb0.y;
            lb = fmaf(-0.5f * z, z, la + pb0.z);
            eaB += __expf(la); ebB += __expf(lb);
            la = d[ns][3] + pb1.w; z = (xB - pb1.x) * pb1.y;
            lb = fmaf(-0.5f * z, z, la + pb1.z);
            eaB += __expf(la); ebB += __expf(lb);
        }
        // reduce over the 4 lanes sharing each row
        eaA += __shfl_xor_sync(0xffffffffu, eaA, 1);
        ebA += __shfl_xor_sync(0xffffffffu, ebA, 1);
        eaB += __shfl_xor_sync(0xffffffffu, eaB, 1);
        ebB += __shfl_xor_sync(0xffffffffu, ebB, 1);
        eaA += __shfl_xor_sync(0xffffffffu, eaA, 2);
        ebA += __shfl_xor_sync(0xffffffffu, ebA, 2);
        eaB += __shfl_xor_sync(0xffffffffu, eaB, 2);
        ebB += __shfl_xor_sync(0xffffffffu, ebB, 2);
        if ((lane & 3) == 0) {
            if (r < n)     acc += __logf(ebA) - __logf(eaA);
            if (r + 8 < n) acc += __logf(ebB) - __logf(eaB);
        }
    }

    // block reduction
#pragma unroll
    for (int o = 16; o > 0; o >>= 1) acc += __shfl_xor_sync(0xffffffffu, acc, o);
    if (lane == 0) wpart[w] = acc;
    __syncthreads();
    if (threadIdx.x == 0) {
        float b = 0.f;
#pragma unroll
        for (int i = 0; i < 8; i++) b += wpart[i];
        atomicAdd(&d_acc, (double)b);
    }
}

// Fragment-count Poisson likelihood: 8 cells per CTA, 2 genes per thread
// (float2 accumulators keep regs <= 64 for 4 CTAs/SM), 8-way gene split
// so 512 blocks fill the chip; rwT L2 traffic stays 64 MB.
// lgamma via small-count SMEM table. LAST block writes the final output.
#define CPB 8
#define NSPLIT 8
__global__ void __launch_bounds__(256, 4) k_fragfinal(
        const float* __restrict__ latent,
        const float* __restrict__ libsize,
        const int* __restrict__ cells_oi,
        int n_cells, int ng, float* __restrict__ out) {
    __shared__ float lat_s[CPB * 64];
    __shared__ float lib_s[CPB];
    __shared__ float lgam[32];
    __shared__ float wpart[8];
    int cb = blockIdx.x / NSPLIT;
    int qs = blockIdx.x % NSPLIT;
    int c0 = cb * CPB;
    int nc = min(CPB, n_cells - c0);
    int g_lo = (int)(((long long)ng * qs) / NSPLIT) & ~1;
    int g_hi = (qs == NSPLIT - 1) ? ng : ((int)(((long long)ng * (qs + 1)) / NSPLIT) & ~1);
    if (threadIdx.x < 32) lgam[threadIdx.x] = lgammaf((float)threadIdx.x + 1.0f);
    for (int i = threadIdx.x; i < CPB * 64; i += blockDim.x)
        lat_s[i] = (i < nc * 64) ? latent[c0 * 64 + i] : 0.0f;
    if (threadIdx.x < CPB)
        lib_s[threadIdx.x] = (threadIdx.x < nc) ? libsize[cells_oi[c0 + threadIdx.x]] : 1.0f;
    __syncthreads();

    float acc = 0.0f;
    int ngv = g_lo + ((g_hi - g_lo) & ~1);
    for (int gg = g_lo + threadIdx.x * 2; gg + 1 < ngv; gg += blockDim.x * 2) {
        float2 r[CPB];
#pragma unroll
        for (int j = 0; j < CPB; j++) r[j] = make_float2(0.f, 0.f);
#pragma unroll 8
        for (int l = 0; l < 64; l++) {
            float2 wv = *(const float2*)(d_rwT + l * ng + gg);
#pragma unroll
            for (int j = 0; j < CPB; j++) {
                float lv = lat_s[j * 64 + l];
                r[j].x = fmaf(lv, wv.x, r[j].x);
                r[j].y = fmaf(lv, wv.y, r[j].y);
            }
        }
        float2 rb = *(const float2*)(d_rbg + gg);
#pragma unroll
        for (int j = 0; j < CPB; j++) {
            if (j >= nc) break;
            float lib = lib_s[j];
            int2 cnt = *(const int2*)(d_counts + (size_t)(c0 + j) * ng + gg);
            float fe, lf;
            fe = rb.x * __expf(r[j].x) * lib; lf = -fe;
            if (cnt.x) lf += (float)cnt.x * __logf(fe) - (cnt.x < 32 ? lgam[cnt.x] : lgammaf((float)cnt.x + 1.0f));
            acc += lf;
            fe = rb.y * __expf(r[j].y) * lib; lf = -fe;
            if (cnt.y) lf += (float)cnt.y * __logf(fe) - (cnt.y < 32 ? lgam[cnt.y] : lgammaf((float)cnt.y + 1.0f));
            acc += lf;
        }
    }
    // scalar tail genes of this split
    for (int gg = ngv + threadIdx.x; gg < g_hi; gg += blockDim.x) {
        for (int j = 0; j < nc; j++) {
            float rho = 0.f;
            for (int l = 0; l < 64; l++)
                rho = fmaf(lat_s[j * 64 + l], d_rwT[l * ng + gg], rho);
            float fe = d_rbg[gg] * __expf(rho) * lib_s[j];
            int c = d_counts[(size_t)(c0 + j) * ng + gg];
            float lf = -fe;
            if (c) lf += (float)c * __logf(fe) - (c < 32 ? lgam[c] : lgammaf((float)c + 1.0f));
            acc += lf;
        }
    }

#pragma unroll
    for (int o = 16; o > 0; o >>= 1) acc += __shfl_xor_sync(0xffffffffu, acc, o);
    int lane = threadIdx.x & 31, w = threadIdx.x >> 5;
    if (lane == 0) wpart[w] = acc;
    __syncthreads();
    if (threadIdx.x == 0) {
        float b = 0.f;
#pragma unroll
        for (int i = 0; i < 8; i++) b += wpart[i];
        atomicAdd(&d_acc, (double)b);
        __threadfence();
        if (atomicAdd(&d_done_f, 1) == gridDim.x - 1) {
            double v = atomicAdd(&d_acc, 0.0);   // L2-coherent read
            out[0] = (float)(-v);
        }
    }
}

// ---------------- launch ----------------
extern "C" void kernel_launch(void* const* d_in, const int* in_sizes, int n_in,
                              void* d_out, int out_size) {
    const int*   lcg      = (const int*)d_in[0];    // local_cellxgene_ix [n_frags]
    const float* coords   = (const float*)d_in[1];  // cut_coordinates [n_cuts]
    const float* latent   = (const float*)d_in[2];  // [n_cells, 64]
    const int*   genes_oi = (const int*)d_in[3];    // [n_genes]
    const int*   cells_oi = (const int*)d_in[4];    // [n_cells]
    const int*   clcg     = (const int*)d_in[5];    // cut_local_cellxgene_ix [n_cuts]
    const int*   clg      = (const int*)d_in[6];    // cut_local_gene_ix [n_cuts]
    // d_in[7], d_in[8] = n_cells, n_genes scalars (derived from sizes instead)
    const float* loc_w    = (const float*)d_in[9];
    const float* scale_w  = (const float*)d_in[10];
    const float* logit_w  = (const float*)d_in[11];
    const float* lw       = (const float*)d_in[12]; // logit_weight [20000,64,32]
    const float* rw       = (const float*)d_in[13]; // rho_weight [20000,64]
    const float* rho_bias = (const float*)d_in[14];
    const float* libsize  = (const float*)d_in[15];

    int n_frags = in_sizes[0];
    int n_cuts  = in_sizes[1];
    int n_cells = in_sizes[2] / 64;
    int n_genes = in_sizes[3];
    int ncg = n_cells * n_genes;

    float* out = (float*)d_out;
    (void)n_in; (void)out_size;

    k_zprep<<<256, 256>>>(genes_oi, loc_w, scale_w, logit_w, rw, rho_bias, latent, n_cells, ncg, n_genes);
    k_gather<<<148, 512>>>(clcg, clg, coords, lcg, n_cuts, n_frags, n_genes);
    k_mix<<<n_genes, 256>>>(genes_oi, lw, n_genes);
    int nfb = ((n_cells + CPB - 1) / CPB) * NSPLIT;
    k_fragfinal<<<nfb, 256>>>(latent, libsize, cells_oi, n_cells, n_genes, out);
}

// round 15
// speedup vs baseline: 1.0257x; 1.0257x over previous
#include <cuda_runtime.h>
#include <cuda_bf16.h>
#include <math.h>
#include <stdint.h>

// ---------------- scratch (no allocations allowed) ----------------
#define NGMAX   4096        // max local genes
#define GCAP    1024        // bucket capacity per gene (mean ~250, sigma ~16)
#define NCGMAX  2048000     // max n_cells * n_genes
#define NCELLMAX 65536      // cell index fits 16 bits

__device__ int    d_hist[NGMAX];             // per-gene cut count / cursor
__device__ int2   d_info[NGMAX * GCAP];      // bucketed: {cell | (g2<<16), coord bits}
__device__ int    d_counts[NCGMAX];
__device__ float4 d_prm[NGMAX * 32];         // {loc, 1/scale, -log(scale)-0.5*log(2pi), logit_w}
__device__ uint32_t d_latbf[NCELLMAX * 32];  // latent rows as bf16x2 (128 B per cell)
__device__ float  d_rwT[64 * NGMAX];         // gathered+transposed rho_weight: [l][g]
__device__ float  d_rbg[NGMAX];              // gathered rho_bias
__device__ double d_acc;                     // likelihood accumulator
__device__ int    d_done_f;                  // frag completion ticket

__device__ __forceinline__ uint32_t pack_bf16(float lo, float hi) {
    uint32_t r;
    asm("cvt.rn.bf16x2.f32 %0, %1, %2;" : "=r"(r) : "f"(hi), "f"(lo));
    return r;
}

// 256-bit load (Blackwell): two adjacent float4s in one instruction.
__device__ __forceinline__ void ldg256(const float4* p, float4& a, float4& b) {
    asm("ld.global.v8.f32 {%0,%1,%2,%3,%4,%5,%6,%7}, [%8];"
        : "=f"(a.x), "=f"(a.y), "=f"(a.z), "=f"(a.w),
          "=f"(b.x), "=f"(b.y), "=f"(b.z), "=f"(b.w)
        : "l"(p));
}

// ---------------- kernels ----------------

// zero scratch (hist, counts, accumulators) — must precede k_gather
__global__ void k_zero(int ncg, int ng) {
    int i = blockIdx.x * blockDim.x + threadIdx.x;
    int stride = gridDim.x * blockDim.x;
    int ncg4 = ncg >> 2;
    int4* c4 = (int4*)d_counts;
    int4 z4 = make_int4(0, 0, 0, 0);
    for (int j = i; j < ncg4; j += stride) c4[j] = z4;
    for (int j = (ncg4 << 2) + i; j < ncg; j += stride) d_counts[j] = 0;
    for (int j = i; j < ng; j += stride) d_hist[j] = 0;
    if (i == 0) { d_acc = 0.0; d_done_f = 0; }
}

// gathered per-gene parameter tables + bf16 latent (independent of k_zero)
__global__ void k_ztables(const int* __restrict__ genes_oi,
                          const float* __restrict__ loc_w,
                          const float* __restrict__ scale_w,
                          const float* __restrict__ logit_w,
                          const float* __restrict__ rho_weight,
                          const float* __restrict__ rho_bias,
                          const float* __restrict__ latent,
                          int n_cells, int ng) {
    int i = blockIdx.x * blockDim.x + threadIdx.x;
    int stride = gridDim.x * blockDim.x;
    for (int j = i; j < ng * 32; j += stride) {
        int g = j >> 5, c = j & 31;
        int gene = genes_oi[g];
        float lwv = logit_w[gene * 32 + c];
        float loc = 1.0f / (1.0f + expf(-loc_w[gene * 32 + c]));
        float sc  = 1e-5f + expf(scale_w[gene * 32 + c]);
        d_prm[j] = make_float4(loc, 1.0f / sc, -logf(sc) - 0.91893853320467274f, lwv);
    }
    for (int j = i; j < ng * 64; j += stride) {
        int g = j % ng, l = j / ng;
        d_rwT[l * ng + g] = rho_weight[(size_t)genes_oi[g] * 64 + l];
    }
    for (int j = i; j < ng; j += stride) d_rbg[j] = rho_bias[genes_oi[j]];
    for (int j = i; j < n_cells * 32; j += stride) {
        float2 v = *(const float2*)(latent + 2 * j);
        d_latbf[j] = pack_bf16(v.x, v.y);
    }
}

// Fused gather: direct-bucket scatter of cuts by gene (no scan needed) +
// fragment count histogram. One pass over clcg/clg/coords/lcg.
__global__ void __launch_bounds__(512) k_gather(
        const int* __restrict__ clcg,
        const int* __restrict__ clg,
        const float* __restrict__ coords,
        const int* __restrict__ lcg,
        int n_cuts, int n_frags, int ng) {
    int i0 = blockIdx.x * blockDim.x + threadIdx.x;
    int stride = gridDim.x * blockDim.x;
    for (int k = i0; k < n_cuts; k += stride) {
        int v = clcg[k];
        int g = v % ng;
        int cell = v / ng;
        int p = atomicAdd(&d_hist[g], 1);
        if (p < GCAP)
            d_info[(g << 10) + p] = make_int2(cell | (clg[k] << 16), __float_as_int(coords[k]));
    }
    for (int f = i0; f < n_frags; f += stride)
        atomicAdd(&d_counts[lcg[f]], 1);
}

// Mixture log-likelihood via tensor cores: one CTA per local gene, one warp
// per 16-cut tile. delta[16,32] = Lat[16,64](bf16) x W[64,32](bf16) with
// mma.sync.m16n8k16 (4 k-steps x 4 n-tiles).
__global__ void __launch_bounds__(256, 4) k_mix(
        const int* __restrict__ genes_oi,
        const float* __restrict__ logit_weight,
        int ng) {
    __shared__ uint32_t sbB[4 * 4 * 32 * 2];            // 4 KB, [ks][ns][lane][j]
    __shared__ __align__(16) unsigned char sA[8][2048]; // 16 KB: 16 rows x 128 B per warp
    __shared__ float wpart[8];
    int g = blockIdx.x;
    int lane = threadIdx.x & 31;
    int w = threadIdx.x >> 5;

    const float* lwg = logit_weight + (size_t)genes_oi[g] * 2048;

    // B-fragment table: entry ((ks*4+ns)*32 + le)*2 + j:
    // c = ns*8 + (le>>2), k0 = ks*16 + (le&3)*2 + j*8, packed {B[k0][c], B[k0+1][c]}
    for (int idx = threadIdx.x; idx < 1024; idx += 256) {
        int j  = idx & 1;
        int le = (idx >> 1) & 31;
        int ns = (idx >> 6) & 3;
        int ks = idx >> 8;
        int c  = ns * 8 + (le >> 2);
        int k0 = ks * 16 + (le & 3) * 2 + j * 8;
        sbB[idx] = pack_bf16(lwg[k0 * 32 + c], lwg[(k0 + 1) * 32 + c]);
    }
    int cnt = min(d_hist[g], GCAP);
    int s0 = g << 10;
    int s1 = s0 + cnt;
    __syncthreads();

    float acc = 0.0f;
    int r  = lane >> 2;
    int cq = (lane & 3) * 2;
    uint32_t wb = (uint32_t)__cvta_generic_to_shared(sA[w]);
    int lm_row = ((lane >> 3) & 1) * 8 + (lane & 7);
    int lm_half = lane >> 4;

    for (int ts = s0 + 16 * w; ts < s1; ts += 128) {
        int n = min(16, s1 - ts);

        // tile info: lanes 0..15 hold one cut each
        int ix = 0;
        float xl = 0.0f;
        if (lane < 16 && ts + lane < s1) {
            int2 ii = d_info[ts + lane];
            ix = ii.x;
            xl = __int_as_float(ii.y);
        }

        // ---- stage 16 bf16 rows (full-line cooperative, swizzled) ----
        __syncwarp();   // previous tile's ldmatrix reads complete
#pragma unroll
        for (int it = 0; it < 4; it++) {
            int q = it * 32 + lane;        // chunk id 0..127
            int row = q >> 3, ch = q & 7;
            int cell = __shfl_sync(0xffffffffu, ix, row) & 0xffff;
            uint4 v = *((const uint4*)d_latbf + cell * 8 + ch);
            uint32_t ad = wb + row * 128 + ((ch ^ (row & 7)) << 4);
            asm volatile("st.shared.v4.b32 [%0], {%1,%2,%3,%4};"
                         :: "r"(ad), "r"(v.x), "r"(v.y), "r"(v.z), "r"(v.w));
        }
        __syncwarp();

        // ---- mma: delta[16,32] via ldmatrix per k-step ----
        float d[4][4];
#pragma unroll
        for (int ns = 0; ns < 4; ns++)
#pragma unroll
            for (int j = 0; j < 4; j++) d[ns][j] = 0.0f;

#pragma unroll
        for (int ks = 0; ks < 4; ks++) {
            int chunk = ks * 2 + lm_half;
            uint32_t ad = wb + lm_row * 128 + ((chunk ^ (lm_row & 7)) << 4);
            uint32_t a0, a1, a2, a3;
            asm volatile("ldmatrix.sync.aligned.m8n8.x4.shared.b16 {%0,%1,%2,%3}, [%4];"
                         : "=r"(a0), "=r"(a1), "=r"(a2), "=r"(a3) : "r"(ad));
#pragma unroll
            for (int ns = 0; ns < 4; ns++) {
                uint2 bb = *(const uint2*)&sbB[((ks * 4 + ns) * 32 + lane) * 2];
                asm volatile(
                    "mma.sync.aligned.m16n8k16.row.col.f32.bf16.bf16.f32 "
                    "{%0,%1,%2,%3}, {%4,%5,%6,%7}, {%8,%9}, {%0,%1,%2,%3};"
                    : "+f"(d[ns][0]), "+f"(d[ns][1]), "+f"(d[ns][2]), "+f"(d[ns][3])
                    : "r"(a0), "r"(a1), "r"(a2), "r"(a3), "r"(bb.x), "r"(bb.y));
            }
        }

        // ---- epilogue: rows r and r+8, comps ns*8 + cq + {0,1} ----
        int ixA = __shfl_sync(0xffffffffu, ix, r);
        int ixB = __shfl_sync(0xffffffffu, ix, r + 8);
        float xA = __shfl_sync(0xffffffffu, xl, r);
        float xB = __shfl_sync(0xffffffffu, xl, r + 8);
        const float4* prmA = d_prm + (((unsigned)ixA) >> 16) * 32;
        const float4* prmB = d_prm + (((unsigned)ixB) >> 16) * 32;
        float eaA = 0.f, ebA = 0.f, eaB = 0.f, ebB = 0.f;
#pragma unroll
        for (int ns = 0; ns < 4; ns++) {
            int c0 = ns * 8 + cq;
            float4 pa0, pa1, pb0, pb1;
            ldg256(prmA + c0, pa0, pa1);
            ldg256(prmB + c0, pb0, pb1);
            float la, z, lb;
            la = d[ns][0] + pa0.w; z = (xA - pa0.x) * pa0.y;
            lb = fmaf(-0.5f * z, z, la + pa0.z);
            eaA += __expf(la); ebA += __expf(lb);
            la = d[ns][1] + pa1.w; z = (xA - pa1.x) * pa1.y;
            lb = fmaf(-0.5f * z, z, la + pa1.z);
            eaA += __expf(la); ebA += __expf(lb);
            la = d[ns][2] + pb0.w; z = (xB - pb0.x) * pb0.y;
            lb = fmaf(-0.5f * z, z, la + pb0.z);
            eaB += __expf(la); ebB += __expf(lb);
            la = d[ns][3] + pb1.w; z = (xB - pb1.x) * pb1.y;
            lb = fmaf(-0.5f * z, z, la + pb1.z);
            eaB += __expf(la); ebB += __expf(lb);
        }
        // reduce over the 4 lanes sharing each row
        eaA += __shfl_xor_sync(0xffffffffu, eaA, 1);
        ebA += __shfl_xor_sync(0xffffffffu, ebA, 1);
        eaB += __shfl_xor_sync(0xffffffffu, eaB, 1);
        ebB += __shfl_xor_sync(0xffffffffu, ebB, 1);
        eaA += __shfl_xor_sync(0xffffffffu, eaA, 2);
        ebA += __shfl_xor_sync(0xffffffffu, ebA, 2);
        eaB += __shfl_xor_sync(0xffffffffu, eaB, 2);
        ebB += __shfl_xor_sync(0xffffffffu, ebB, 2);
        if ((lane & 3) == 0) {
            if (r < n)     acc += __logf(ebA) - __logf(eaA);
            if (r + 8 < n) acc += __logf(ebB) - __logf(eaB);
        }
    }

    // block reduction
#pragma unroll
    for (int o = 16; o > 0; o >>= 1) acc += __shfl_xor_sync(0xffffffffu, acc, o);
    if (lane == 0) wpart[w] = acc;
    __syncthreads();
    if (threadIdx.x == 0) {
        float b = 0.f;
#pragma unroll
        for (int i = 0; i < 8; i++) b += wpart[i];
        atomicAdd(&d_acc, (double)b);
    }
}

// Fragment-count Poisson likelihood: 8 cells per CTA, 2 genes per thread,
// 8-way gene split. lgamma via small-count SMEM table. LAST finishing block
// writes the final output (works regardless of mix/frag completion order,
// since by then both kernels' d_acc atomics are globally visible only if
// mix precedes in the graph — here frag runs CONCURRENT with mix, so the
// final write must wait for BOTH: we add mix's own ticket to the count).
#define CPB 8
#define NSPLIT 8
__global__ void __launch_bounds__(256, 4) k_fragfinal(
        const float* __restrict__ latent,
        const float* __restrict__ libsize,
        const int* __restrict__ cells_oi,
        int n_cells, int ng, float* __restrict__ out, int total_tickets) {
    __shared__ float lat_s[CPB * 64];
    __shared__ float lib_s[CPB];
    __shared__ float lgam[32];
    __shared__ float wpart[8];
    int cb = blockIdx.x / NSPLIT;
    int qs = blockIdx.x % NSPLIT;
    int c0 = cb * CPB;
    int nc = min(CPB, n_cells - c0);
    int g_lo = (int)(((long long)ng * qs) / NSPLIT) & ~1;
    int g_hi = (qs == NSPLIT - 1) ? ng : ((int)(((long long)ng * (qs + 1)) / NSPLIT) & ~1);
    if (threadIdx.x < 32) lgam[threadIdx.x] = lgammaf((float)threadIdx.x + 1.0f);
    for (int i = threadIdx.x; i < CPB * 64; i += blockDim.x)
        lat_s[i] = (i < nc * 64) ? latent[c0 * 64 + i] : 0.0f;
    if (threadIdx.x < CPB)
        lib_s[threadIdx.x] = (threadIdx.x < nc) ? libsize[cells_oi[min(c0 + threadIdx.x, n_cells - 1)]] : 1.0f;
    __syncthreads();

    float acc = 0.0f;
    int ngv = g_lo + ((g_hi - g_lo) & ~1);
    for (int gg = g_lo + threadIdx.x * 2; gg + 1 < ngv; gg += blockDim.x * 2) {
        float2 r[CPB];
#pragma unroll
        for (int j = 0; j < CPB; j++) r[j] = make_float2(0.f, 0.f);
#pragma unroll 8
        for (int l = 0; l < 64; l++) {
            float2 wv = *(const float2*)(d_rwT + l * ng + gg);
#pragma unroll
            for (int j = 0; j < CPB; j++) {
                float lv = lat_s[j * 64 + l];
                r[j].x = fmaf(lv, wv.x, r[j].x);
                r[j].y = fmaf(lv, wv.y, r[j].y);
            }
        }
        float2 rb = *(const float2*)(d_rbg + gg);
#pragma unroll
        for (int j = 0; j < CPB; j++) {
            if (j >= nc) break;
            float lib = lib_s[j];
            int2 cnt = *(const int2*)(d_counts + (size_t)(c0 + j) * ng + gg);
            float fe, lf;
            fe = rb.x * __expf(r[j].x) * lib; lf = -fe;
            if (cnt.x) lf += (float)cnt.x * __logf(fe) - (cnt.x < 32 ? lgam[cnt.x] : lgammaf((float)cnt.x + 1.0f));
            acc += lf;
            fe = rb.y * __expf(r[j].y) * lib; lf = -fe;
            if (cnt.y) lf += (float)cnt.y * __logf(fe) - (cnt.y < 32 ? lgam[cnt.y] : lgammaf((float)cnt.y + 1.0f));
            acc += lf;
        }
    }
    // scalar tail genes of this split
    for (int gg = ngv + threadIdx.x; gg < g_hi; gg += blockDim.x) {
        for (int j = 0; j < nc; j++) {
            float rho = 0.f;
            for (int l = 0; l < 64; l++)
                rho = fmaf(lat_s[j * 64 + l], d_rwT[l * ng + gg], rho);
            float fe = d_rbg[gg] * __expf(rho) * lib_s[j];
            int c = d_counts[(size_t)(c0 + j) * ng + gg];
            float lf = -fe;
            if (c) lf += (float)c * __logf(fe) - (c < 32 ? lgam[c] : lgammaf((float)c + 1.0f));
            acc += lf;
        }
    }

#pragma unroll
    for (int o = 16; o > 0; o >>= 1) acc += __shfl_xor_sync(0xffffffffu, acc, o);
    int lane = threadIdx.x & 31, w = threadIdx.x >> 5;
    if (lane == 0) wpart[w] = acc;
    __syncthreads();
    if (threadIdx.x == 0) {
        float b = 0.f;
#pragma unroll
        for (int i = 0; i < 8; i++) b += wpart[i];
        atomicAdd(&d_acc, (double)b);
    }
    (void)total_tickets; (void)out;
}

// Final output write — tiny kernel after the mix/frag join.
__global__ void k_final(float* out) {
    if (threadIdx.x == 0) out[0] = (float)(-d_acc);
}

// ---------------- launch ----------------
extern "C" void kernel_launch(void* const* d_in, const int* in_sizes, int n_in,
                              void* d_out, int out_size) {
    const int*   lcg      = (const int*)d_in[0];    // local_cellxgene_ix [n_frags]
    const float* coords   = (const float*)d_in[1];  // cut_coordinates [n_cuts]
    const float* latent   = (const float*)d_in[2];  // [n_cells, 64]
    const int*   genes_oi = (const int*)d_in[3];    // [n_genes]
    const int*   cells_oi = (const int*)d_in[4];    // [n_cells]
    const int*   clcg     = (const int*)d_in[5];    // cut_local_cellxgene_ix [n_cuts]
    const int*   clg      = (const int*)d_in[6];    // cut_local_gene_ix [n_cuts]
    const float* loc_w    = (const float*)d_in[9];
    const float* scale_w  = (const float*)d_in[10];
    const float* logit_w  = (const float*)d_in[11];
    const float* lw       = (const float*)d_in[12]; // logit_weight [20000,64,32]
    const float* rw       = (const float*)d_in[13]; // rho_weight [20000,64]
    const float* rho_bias = (const float*)d_in[14];
    const float* libsize  = (const float*)d_in[15];

    int n_frags = in_sizes[0];
    int n_cuts  = in_sizes[1];
    int n_cells = in_sizes[2] / 64;
    int n_genes = in_sizes[3];
    int ncg = n_cells * n_genes;

    float* out = (float*)d_out;
    (void)n_in; (void)out_size;

    // Side stream + events for parallel branches in the captured graph.
    // Created fresh per call and intentionally NOT destroyed (kernel_launch
    // is invoked only a handful of times; destroying mid-capture risks
    // invalidating the capture). No device memory is involved.
    cudaStream_t sB;
    cudaEvent_t eFork1, eJoin1, eFork2, eJoin2;
    cudaStreamCreateWithFlags(&sB, cudaStreamNonBlocking);
    cudaEventCreateWithFlags(&eFork1, cudaEventDisableTiming);
    cudaEventCreateWithFlags(&eJoin1, cudaEventDisableTiming);
    cudaEventCreateWithFlags(&eFork2, cudaEventDisableTiming);
    cudaEventCreateWithFlags(&eJoin2, cudaEventDisableTiming);

    cudaStream_t s0 = 0;   // capture-origin (legacy) stream

    // fork: ztables runs parallel with zero+gather
    cudaEventRecord(eFork1, s0);
    cudaStreamWaitEvent(sB, eFork1, 0);
    k_ztables<<<256, 256, 0, sB>>>(genes_oi, loc_w, scale_w, logit_w, rw, rho_bias,
                                   latent, n_cells, n_genes);
    k_zero<<<256, 256>>>(ncg, n_genes);
    k_gather<<<148, 512>>>(clcg, clg, coords, lcg, n_cuts, n_frags, n_genes);
    cudaEventRecord(eJoin1, sB);
    cudaStreamWaitEvent(s0, eJoin1, 0);

    // fork: frag runs parallel with mix
    int nfb = ((n_cells + CPB - 1) / CPB) * NSPLIT;
    cudaEventRecord(eFork2, s0);
    cudaStreamWaitEvent(sB, eFork2, 0);
    k_fragfinal<<<nfb, 256, 0, sB>>>(latent, libsize, cells_oi, n_cells, n_genes, out, 0);
    k_mix<<<n_genes, 256>>>(genes_oi, lw, n_genes);
    cudaEventRecord(eJoin2, sB);
    cudaStreamWaitEvent(s0, eJoin2, 0);

    // final output after both branches
    k_final<<<1, 32>>>(out);
}